// round 13
// baseline (speedup 1.0000x reference)
#include <cuda_runtime.h>
#include <cuda_fp16.h>
#include <cstdint>

#define BB 64
#define TT 256
#define II 1024
#define HH 2048
#define OO 1024

// ---------------- device scratch ----------------
__device__ __half g_xh[(size_t)BB * TT * II];
__device__ __half g_Wax[(size_t)HH * II];
__device__ __half g_Waa[(size_t)HH * HH];
__device__ __half g_Wya[(size_t)OO * HH];
__device__ float  g_Z[(size_t)TT * BB * HH];                 // x W_ax^T + b_ax + b_aa
__device__ __half g_ahist[(size_t)(TT + 1) * BB * HH];       // all hidden states
__device__ unsigned g_barh[64];                               // [0] and [32]: per-mh counters

// ---------------- helpers ----------------
__device__ __forceinline__ uint32_t sptr(const void* p) {
    return (uint32_t)__cvta_generic_to_shared(p);
}
__device__ __forceinline__ void cp_async16(const void* dst_smem, const void* src) {
    asm volatile("cp.async.cg.shared.global [%0], [%1], 16;"
                 :: "r"(sptr(dst_smem)), "l"(src));
}
__device__ __forceinline__ void cp_commit() { asm volatile("cp.async.commit_group;"); }
__device__ __forceinline__ void cp_wait0()  { asm volatile("cp.async.wait_group 0;"); }
__device__ __forceinline__ void cp_wait1()  { asm volatile("cp.async.wait_group 1;"); }

__device__ __forceinline__ void ldsm4(uint32_t& r0, uint32_t& r1, uint32_t& r2, uint32_t& r3,
                                      const void* p) {
    asm volatile("ldmatrix.sync.aligned.m8n8.x4.shared.b16 {%0,%1,%2,%3},[%4];"
                 : "=r"(r0), "=r"(r1), "=r"(r2), "=r"(r3) : "r"(sptr(p)));
}
__device__ __forceinline__ void mma16816(float* c, const uint32_t* a,
                                         uint32_t b0, uint32_t b1) {
    asm volatile("mma.sync.aligned.m16n8k16.row.col.f32.f16.f16.f32 "
                 "{%0,%1,%2,%3},{%4,%5,%6,%7},{%8,%9},{%0,%1,%2,%3};"
                 : "+f"(c[0]), "+f"(c[1]), "+f"(c[2]), "+f"(c[3])
                 : "r"(a[0]), "r"(a[1]), "r"(a[2]), "r"(a[3]), "r"(b0), "r"(b1));
}
// fp16-accumulate variant: D/C are 2 regs (fp16x2 each)
__device__ __forceinline__ void mma16816_h(uint32_t* c, const uint32_t* a,
                                           uint32_t b0, uint32_t b1) {
    asm volatile("mma.sync.aligned.m16n8k16.row.col.f16.f16.f16.f16 "
                 "{%0,%1},{%2,%3,%4,%5},{%6,%7},{%0,%1};"
                 : "+r"(c[0]), "+r"(c[1])
                 : "r"(a[0]), "r"(a[1]), "r"(a[2]), "r"(a[3]), "r"(b0), "r"(b1));
}
__device__ __forceinline__ float sigf(float v) { return 1.0f / (1.0f + __expf(-v)); }

__device__ __forceinline__ unsigned ld_acq(const unsigned* p) {
    unsigned v;
    asm volatile("ld.acquire.gpu.u32 %0, [%1];" : "=r"(v) : "l"(p));
    return v;
}
__device__ __forceinline__ void red_rel_add1(unsigned* p) {
    asm volatile("red.release.gpu.add.u32 [%0], 1;" :: "l"(p));
}

// ---------------- prep (vectorized x4) ----------------
#define NX  ((size_t)BB * TT * II)
#define NAA ((size_t)HH * HH)
#define NAX ((size_t)HH * II)
#define NYA ((size_t)OO * HH)
#define NA0 ((size_t)BB * HH)
#define NPREP4 ((NX + NAA + NAX + NYA + NA0) / 4)

__device__ __forceinline__ void cvt4(__half* dst, const float* src, size_t i4) {
    float4 v = *(const float4*)(src + i4 * 4);
    __half2 h0 = __floats2half2_rn(v.x, v.y);
    __half2 h1 = __floats2half2_rn(v.z, v.w);
    *(uint2*)(dst + i4 * 4) = make_uint2(*(uint32_t*)&h0, *(uint32_t*)&h1);
}

__global__ void prep_kernel(const float* __restrict__ x, const float* __restrict__ Waa,
                            const float* __restrict__ Wax, const float* __restrict__ Wya) {
    size_t i = (size_t)blockIdx.x * blockDim.x + threadIdx.x;
    if (i < 64) g_barh[i] = 0u;
    if (i < NX / 4) { cvt4(g_xh, x, i); return; }
    i -= NX / 4;
    if (i < NAA / 4) { cvt4(g_Waa, Waa, i); return; }
    i -= NAA / 4;
    if (i < NAX / 4) { cvt4(g_Wax, Wax, i); return; }
    i -= NAX / 4;
    if (i < NYA / 4) { cvt4(g_Wya, Wya, i); return; }
    i -= NYA / 4;
    if (i < NA0 / 4) { *(uint2*)(g_ahist + i * 4) = make_uint2(0u, 0u); }  // a_0 = 0
}

// ---------------- big parallel GEMM (xproj MODE 0 / ypass MODE 1) ----------------
#define XP_SMEM (2 * (2 * 128 * 72 * 2))

template <int MODE>
__global__ void __launch_bounds__(256) big_gemm(const float* __restrict__ c0,
                                                const float* __restrict__ c1,
                                                float* __restrict__ outp) {
    constexpr int KD = (MODE == 0) ? II : HH;
    constexpr int NCHX = KD / 64;
    extern __shared__ __align__(16) unsigned char smraw[];
    __half* As = (__half*)smraw;                       // [2][128][72]
    __half* Bs = (__half*)(smraw + 2 * 128 * 72 * 2);  // [2][128][72]

    const int tid = threadIdx.x;
    const int lane = tid & 31, warp = tid >> 5;
    const int n0 = blockIdx.x * 128;
    const int m0 = blockIdx.y * 128;
    const int wm = (warp >> 1) * 32;
    const int wn = (warp & 1) * 64;
    const int gr = lane >> 2, q = lane & 3;

    const int arow = ((lane >> 3) & 1) * 8 + (lane & 7);
    const int akoff = (lane >> 4) * 8;
    const int brow = (lane >> 4) * 8 + (lane & 7);
    const int bkoff = ((lane >> 3) & 1) * 8;

    const __half* Wg = (MODE == 0) ? g_Wax : g_Wya;

    float acc[2][8][4];
#pragma unroll
    for (int f = 0; f < 2; ++f)
#pragma unroll
        for (int bt = 0; bt < 8; ++bt)
#pragma unroll
            for (int c = 0; c < 4; ++c) acc[f][bt][c] = 0.0f;

    auto load_chunk = [&](int buf, int ck) {
#pragma unroll
        for (int r = 0; r < 4; ++r) {
            int u = tid + r * 256;
            int row = u >> 3, cg = u & 7;
            int m = m0 + row;
            const __half* asrc;
            if (MODE == 0) {
                int t = m >> 6, b = m & 63;
                asrc = g_xh + ((size_t)b * TT + t) * II + ck * 64 + cg * 8;
            } else {
                asrc = g_ahist + (size_t)(m + 64) * HH + ck * 64 + cg * 8;
            }
            cp_async16(As + buf * (128 * 72) + row * 72 + cg * 8, asrc);
            cp_async16(Bs + buf * (128 * 72) + row * 72 + cg * 8,
                       Wg + (size_t)(n0 + row) * KD + ck * 64 + cg * 8);
        }
    };

    load_chunk(0, 0);
    cp_commit();
    for (int ck = 0; ck < NCHX; ++ck) {
        if (ck + 1 < NCHX) { load_chunk((ck + 1) & 1, ck + 1); cp_commit(); cp_wait1(); }
        else cp_wait0();
        __syncthreads();
        const __half* Ab = As + (ck & 1) * (128 * 72);
        const __half* Bb = Bs + (ck & 1) * (128 * 72);
#pragma unroll
        for (int s = 0; s < 4; ++s) {
            uint32_t a[2][4];
#pragma unroll
            for (int f = 0; f < 2; ++f)
                ldsm4(a[f][0], a[f][1], a[f][2], a[f][3],
                      Ab + (wm + f * 16 + arow) * 72 + s * 16 + akoff);
#pragma unroll
            for (int bp = 0; bp < 4; ++bp) {
                uint32_t b0, b1, b2, b3;
                ldsm4(b0, b1, b2, b3,
                      Bb + (wn + bp * 16 + brow) * 72 + s * 16 + bkoff);
#pragma unroll
                for (int f = 0; f < 2; ++f) {
                    mma16816(acc[f][2 * bp],     a[f], b0, b1);
                    mma16816(acc[f][2 * bp + 1], a[f], b2, b3);
                }
            }
        }
        __syncthreads();
    }

    float bs0[8], bs1[8];
#pragma unroll
    for (int bt = 0; bt < 8; ++bt) {
        int n = n0 + wn + bt * 8 + 2 * q;
        if (MODE == 0) { bs0[bt] = c0[n] + c1[n]; bs1[bt] = c0[n + 1] + c1[n + 1]; }
        else           { bs0[bt] = c0[n];         bs1[bt] = c0[n + 1]; }
    }
#pragma unroll
    for (int f = 0; f < 2; ++f) {
#pragma unroll
        for (int bt = 0; bt < 8; ++bt) {
            int mlo = wm + f * 16 + gr;
            int n = wn + bt * 8 + 2 * q;
            if (MODE == 0) {
                size_t zi = (size_t)(m0 + mlo) * HH + n0 + n;
                *(float2*)(g_Z + zi) =
                    make_float2(acc[f][bt][0] + bs0[bt], acc[f][bt][1] + bs1[bt]);
                *(float2*)(g_Z + zi + (size_t)8 * HH) =
                    make_float2(acc[f][bt][2] + bs0[bt], acc[f][bt][3] + bs1[bt]);
            } else {
                size_t oi = (size_t)(m0 + mlo) * OO + n0 + n;
                *(float2*)(outp + oi) =
                    make_float2(sigf(acc[f][bt][0] + bs0[bt]), sigf(acc[f][bt][1] + bs1[bt]));
                *(float2*)(outp + oi + (size_t)8 * OO) =
                    make_float2(sigf(acc[f][bt][2] + bs0[bt]), sigf(acc[f][bt][3] + bs1[bt]));
            }
        }
    }
}

// ---------------- persistent recurrence: aa ONLY, 128 CTAs ----------------
// fp16 accumulation within each K=64 chunk, fp32 master accumulation across
// chunks. Per-mh split release/acquire barrier (two independent 64-arrival
// barriers on separate L2 lines).
#define NCTA_R 128
#define WPAD 2056
#define NCH 8
#define ASTR 264                                     // 256 + 8 pad
#define ABUFH (32 * ASTR)                            // 8448 halves = 16896 B
#define ZSTR 36
#define OFF_W 0
#define OFF_A (32 * WPAD * 2)                        // 131584
#define OFF_RED (OFF_A + 3 * ABUFH * 2)              // 131584 + 50688 = 182272
#define OFF_Z (OFF_RED + 6 * 16 * 32 * 4)            // + 12288 = 194560
#define PERS_SMEM (OFF_Z + 2 * 32 * ZSTR * 4)        // + 9216 = 203776

__global__ void __launch_bounds__(256) rnn_persistent() {
    extern __shared__ __align__(16) unsigned char smraw[];
    __half* Wsm = (__half*)(smraw + OFF_W);        // [32][WPAD]
    __half* Asm = (__half*)(smraw + OFF_A);        // [3][32][ASTR]
    float*  red = (float*)(smraw + OFF_RED);       // [2 mq][3 part][16][32]
    float*  Zsm = (float*)(smraw + OFF_Z);         // [2][32][ZSTR]

    const int tid = threadIdx.x;
    const int lane = tid & 31, warp = tid >> 5;
    const int cta = blockIdx.x;
    const int slice = cta & 63;
    const int mh = cta >> 6;                 // 0..1
    const int n0 = slice * 32;
    const int row0 = mh * 32;
    unsigned* barp = &g_barh[mh * 32];       // separate 128B lines per half

    // Z slice loader: 32 rows x 32 floats = 256 16B segs, 1/thread
    auto loadZ = [&](int it, int zb) {
        int row = tid >> 3, j = tid & 7;
        cp_async16(Zsm + zb * (32 * ZSTR) + row * ZSTR + j * 4,
                   g_Z + ((size_t)it * 64 + row0 + row) * HH + n0 + j * 4);
    };

    // persistent W_aa slice: 32 rows x 2048 halves; plus Z for step 0
    for (int u = tid; u < 32 * 256; u += 256) {
        int row = u >> 8, cg = u & 255;
        cp_async16(Wsm + row * WPAD + cg * 8, g_Waa + (size_t)(n0 + row) * HH + cg * 8);
    }
    loadZ(0, 0);
    cp_commit();
    cp_wait0();
    __syncthreads();

    const int mq = warp >> 2;          // 0..1 (m16 group within 32 rows)
    const int kq = warp & 3;           // 0..3 (k quarter)
    const int gr = lane >> 2, q = lane & 3;
    const int arow = ((lane >> 3) & 1) * 8 + (lane & 7);
    const int akoff = (lane >> 4) * 8;
    const int brow = (lane >> 4) * 8 + (lane & 7);
    const int bkoff = ((lane >> 3) & 1) * 8;

    // chunk loader: 32 rows x (4 quarters x 64 cols) = 1024 16B segs, 4/thread
    auto loadA = [&](int buf, int c, const __half* a_src) {
#pragma unroll
        for (int r = 0; r < 4; ++r) {
            int idx = tid + r * 256;
            int row = idx >> 5, seg = idx & 31;
            int qq = seg >> 3, j = seg & 7;
            cp_async16(Asm + buf * ABUFH + row * ASTR + qq * 64 + j * 8,
                       a_src + (size_t)(row0 + row) * HH + qq * 512 + c * 64 + j * 8);
        }
    };

    for (int it = 0; it < TT; ++it) {
        const __half* a_cur = g_ahist + (size_t)it * NA0;
        const float* Zb = Zsm + (it & 1) * (32 * ZSTR);

        float acc[4][4];
#pragma unroll
        for (int bs = 0; bs < 4; ++bs)
#pragma unroll
            for (int c = 0; c < 4; ++c) acc[bs][c] = 0.0f;

        loadA(0, 0, a_cur); cp_commit();
        loadA(1, 1, a_cur); cp_commit();

        for (int c = 0; c < NCH; ++c) {
            if (c < NCH - 1) cp_wait1(); else cp_wait0();
            __syncthreads();   // chunk c resident; all warps done with c-1
            if (c + 2 < NCH) { loadA((c + 2) % 3, c + 2, a_cur); cp_commit(); }

            const __half* Ab = Asm + (c % 3) * ABUFH;

            // fp16 chunk accumulators (4 chains x 2 regs)
            uint32_t hacc[4][2];
#pragma unroll
            for (int bs = 0; bs < 4; ++bs) { hacc[bs][0] = 0u; hacc[bs][1] = 0u; }

#pragma unroll
            for (int s = 0; s < 4; ++s) {
                uint32_t a[4];
                ldsm4(a[0], a[1], a[2], a[3],
                      Ab + (mq * 16 + arow) * ASTR + kq * 64 + s * 16 + akoff);
                int bcol = kq * 512 + c * 64 + s * 16 + bkoff;
                uint32_t bl0, bl1, bl2, bl3, bu0, bu1, bu2, bu3;
                ldsm4(bl0, bl1, bl2, bl3, Wsm + brow * WPAD + bcol);
                ldsm4(bu0, bu1, bu2, bu3, Wsm + (brow + 16) * WPAD + bcol);
                mma16816_h(hacc[0], a, bl0, bl1);
                mma16816_h(hacc[1], a, bl2, bl3);
                mma16816_h(hacc[2], a, bu0, bu1);
                mma16816_h(hacc[3], a, bu2, bu3);
            }

            // promote chunk sums to fp32 master accumulators
#pragma unroll
            for (int bs = 0; bs < 4; ++bs) {
                float2 f0 = __half22float2(*(__half2*)&hacc[bs][0]);
                float2 f1 = __half22float2(*(__half2*)&hacc[bs][1]);
                acc[bs][0] += f0.x; acc[bs][1] += f0.y;
                acc[bs][2] += f1.x; acc[bs][3] += f1.y;
            }
        }

        // ---- k-split reduction ----
        if (kq != 0) {
            float* rp = red + (size_t)(mq * 3 + (kq - 1)) * 512;
#pragma unroll
            for (int bs = 0; bs < 4; ++bs) {
                int col = bs * 8 + 2 * q;
                *(float2*)(rp + gr * 32 + col) = make_float2(acc[bs][0], acc[bs][1]);
                *(float2*)(rp + (gr + 8) * 32 + col) = make_float2(acc[bs][2], acc[bs][3]);
            }
        }
        __syncthreads();
        if (kq == 0) {
#pragma unroll
            for (int p = 0; p < 3; ++p) {
                const float* rp = red + (size_t)(mq * 3 + p) * 512;
#pragma unroll
                for (int bs = 0; bs < 4; ++bs) {
                    int col = bs * 8 + 2 * q;
                    float2 v0 = *(const float2*)(rp + gr * 32 + col);
                    float2 v1 = *(const float2*)(rp + (gr + 8) * 32 + col);
                    acc[bs][0] += v0.x; acc[bs][1] += v0.y;
                    acc[bs][2] += v1.x; acc[bs][3] += v1.y;
                }
            }
            __half* adst = g_ahist + (size_t)(it + 1) * NA0;
#pragma unroll
            for (int bs = 0; bs < 4; ++bs) {
                int mloc = mq * 16 + gr;
                int col = bs * 8 + 2 * q;
                int gm = row0 + mloc;
                float2 z0 = *(const float2*)(Zb + mloc * ZSTR + col);
                size_t i0 = (size_t)gm * HH + n0 + col;
                *(__half2*)(adst + i0) =
                    __floats2half2_rn(sigf(acc[bs][0] + z0.x), sigf(acc[bs][1] + z0.y));
                float2 z1 = *(const float2*)(Zb + (mloc + 8) * ZSTR + col);
                size_t i1 = i0 + (size_t)8 * HH;
                *(__half2*)(adst + i1) =
                    __floats2half2_rn(sigf(acc[bs][2] + z1.x), sigf(acc[bs][3] + z1.y));
            }
        }

        // prefetch next step's Z across the barrier (g_Z is static)
        if (it + 1 < TT) { loadZ(it + 1, (it + 1) & 1); cp_commit(); }

        // -------- per-half grid barrier (release/acquire, 64 arrivals) --------
        __syncthreads();                 // all stores of this CTA complete
        if (tid == 0) {
            red_rel_add1(barp);
            unsigned target = (unsigned)(it + 1) * 64u;
            while (ld_acq(barp) < target) { }
        }
        __syncthreads();
    }
}

// ---------------- launch ----------------
extern "C" void kernel_launch(void* const* d_in, const int* in_sizes, int n_in,
                              void* d_out, int out_size) {
    const float* x    = (const float*)d_in[0];
    const float* Waa  = (const float*)d_in[1];
    const float* b_aa = (const float*)d_in[2];
    const float* Wax  = (const float*)d_in[3];
    const float* b_ax = (const float*)d_in[4];
    const float* Wya  = (const float*)d_in[5];
    const float* b_ya = (const float*)d_in[6];
    float* out = (float*)d_out;

    static bool attr_done = false;
    if (!attr_done) {
        cudaFuncSetAttribute(big_gemm<0>, cudaFuncAttributeMaxDynamicSharedMemorySize, XP_SMEM);
        cudaFuncSetAttribute(big_gemm<1>, cudaFuncAttributeMaxDynamicSharedMemorySize, XP_SMEM);
        cudaFuncSetAttribute(rnn_persistent, cudaFuncAttributeMaxDynamicSharedMemorySize, PERS_SMEM);
        attr_done = true;
    }

    int prep_blocks = (int)((NPREP4 + 255) / 256);
    prep_kernel<<<prep_blocks, 256>>>(x, Waa, Wax, Wya);

    dim3 xg(HH / 128, (TT * BB) / 128);   // 16 x 128
    big_gemm<0><<<xg, 256, XP_SMEM>>>(b_ax, b_aa, nullptr);

    rnn_persistent<<<NCTA_R, 256, PERS_SMEM>>>();

    dim3 yg(OO / 128, (TT * BB) / 128);   // 8 x 128
    big_gemm<1><<<yg, 256, XP_SMEM>>>(b_ya, nullptr, out);
}

// round 14
// speedup vs baseline: 1.1002x; 1.1002x over previous
#include <cuda_runtime.h>
#include <cuda_fp16.h>
#include <cstdint>

#define BB 64
#define TT 256
#define II 1024
#define HH 2048
#define OO 1024

// ---------------- device scratch ----------------
__device__ __half g_xh[(size_t)BB * TT * II];
__device__ __half g_Wax[(size_t)HH * II];
__device__ __half g_Waa[(size_t)HH * HH];
__device__ __half g_Wya[(size_t)OO * HH];
__device__ float  g_Z[(size_t)TT * BB * HH];                 // x W_ax^T + b_ax + b_aa
__device__ __half g_ahist[(size_t)(TT + 1) * BB * HH];       // all hidden states
__device__ unsigned g_barh[64];                               // [0] and [32]: per-mh counters

// ---------------- helpers ----------------
__device__ __forceinline__ uint32_t sptr(const void* p) {
    return (uint32_t)__cvta_generic_to_shared(p);
}
__device__ __forceinline__ void cp_async16(const void* dst_smem, const void* src) {
    asm volatile("cp.async.cg.shared.global [%0], [%1], 16;"
                 :: "r"(sptr(dst_smem)), "l"(src));
}
__device__ __forceinline__ void cp_commit() { asm volatile("cp.async.commit_group;"); }
__device__ __forceinline__ void cp_wait0()  { asm volatile("cp.async.wait_group 0;"); }
__device__ __forceinline__ void cp_wait1()  { asm volatile("cp.async.wait_group 1;"); }

__device__ __forceinline__ void ldsm4(uint32_t& r0, uint32_t& r1, uint32_t& r2, uint32_t& r3,
                                      const void* p) {
    asm volatile("ldmatrix.sync.aligned.m8n8.x4.shared.b16 {%0,%1,%2,%3},[%4];"
                 : "=r"(r0), "=r"(r1), "=r"(r2), "=r"(r3) : "r"(sptr(p)));
}
__device__ __forceinline__ void mma16816(float* c, const uint32_t* a,
                                         uint32_t b0, uint32_t b1) {
    asm volatile("mma.sync.aligned.m16n8k16.row.col.f32.f16.f16.f32 "
                 "{%0,%1,%2,%3},{%4,%5,%6,%7},{%8,%9},{%0,%1,%2,%3};"
                 : "+f"(c[0]), "+f"(c[1]), "+f"(c[2]), "+f"(c[3])
                 : "r"(a[0]), "r"(a[1]), "r"(a[2]), "r"(a[3]), "r"(b0), "r"(b1));
}
__device__ __forceinline__ float sigf(float v) { return 1.0f / (1.0f + __expf(-v)); }

__device__ __forceinline__ unsigned ld_acq(const unsigned* p) {
    unsigned v;
    asm volatile("ld.acquire.gpu.u32 %0, [%1];" : "=r"(v) : "l"(p));
    return v;
}
__device__ __forceinline__ void red_rel_add1(unsigned* p) {
    asm volatile("red.release.gpu.add.u32 [%0], 1;" :: "l"(p));
}

// ---------------- prep (vectorized x4) ----------------
#define NX  ((size_t)BB * TT * II)
#define NAA ((size_t)HH * HH)
#define NAX ((size_t)HH * II)
#define NYA ((size_t)OO * HH)
#define NA0 ((size_t)BB * HH)
#define NPREP4 ((NX + NAA + NAX + NYA + NA0) / 4)

__device__ __forceinline__ void cvt4(__half* dst, const float* src, size_t i4) {
    float4 v = *(const float4*)(src + i4 * 4);
    __half2 h0 = __floats2half2_rn(v.x, v.y);
    __half2 h1 = __floats2half2_rn(v.z, v.w);
    *(uint2*)(dst + i4 * 4) = make_uint2(*(uint32_t*)&h0, *(uint32_t*)&h1);
}

__global__ void prep_kernel(const float* __restrict__ x, const float* __restrict__ Waa,
                            const float* __restrict__ Wax, const float* __restrict__ Wya) {
    size_t i = (size_t)blockIdx.x * blockDim.x + threadIdx.x;
    if (i < 64) g_barh[i] = 0u;
    if (i < NX / 4) { cvt4(g_xh, x, i); return; }
    i -= NX / 4;
    if (i < NAA / 4) { cvt4(g_Waa, Waa, i); return; }
    i -= NAA / 4;
    if (i < NAX / 4) { cvt4(g_Wax, Wax, i); return; }
    i -= NAX / 4;
    if (i < NYA / 4) { cvt4(g_Wya, Wya, i); return; }
    i -= NYA / 4;
    if (i < NA0 / 4) { *(uint2*)(g_ahist + i * 4) = make_uint2(0u, 0u); }  // a_0 = 0
}

// ---------------- big parallel GEMM (xproj MODE 0 / ypass MODE 1) ----------------
#define XP_SMEM (2 * (2 * 128 * 72 * 2))

template <int MODE>
__global__ void __launch_bounds__(256) big_gemm(const float* __restrict__ c0,
                                                const float* __restrict__ c1,
                                                float* __restrict__ outp) {
    constexpr int KD = (MODE == 0) ? II : HH;
    constexpr int NCHX = KD / 64;
    extern __shared__ __align__(16) unsigned char smraw[];
    __half* As = (__half*)smraw;                       // [2][128][72]
    __half* Bs = (__half*)(smraw + 2 * 128 * 72 * 2);  // [2][128][72]

    const int tid = threadIdx.x;
    const int lane = tid & 31, warp = tid >> 5;
    const int n0 = blockIdx.x * 128;
    const int m0 = blockIdx.y * 128;
    const int wm = (warp >> 1) * 32;
    const int wn = (warp & 1) * 64;
    const int gr = lane >> 2, q = lane & 3;

    const int arow = ((lane >> 3) & 1) * 8 + (lane & 7);
    const int akoff = (lane >> 4) * 8;
    const int brow = (lane >> 4) * 8 + (lane & 7);
    const int bkoff = ((lane >> 3) & 1) * 8;

    const __half* Wg = (MODE == 0) ? g_Wax : g_Wya;

    float acc[2][8][4];
#pragma unroll
    for (int f = 0; f < 2; ++f)
#pragma unroll
        for (int bt = 0; bt < 8; ++bt)
#pragma unroll
            for (int c = 0; c < 4; ++c) acc[f][bt][c] = 0.0f;

    auto load_chunk = [&](int buf, int ck) {
#pragma unroll
        for (int r = 0; r < 4; ++r) {
            int u = tid + r * 256;
            int row = u >> 3, cg = u & 7;
            int m = m0 + row;
            const __half* asrc;
            if (MODE == 0) {
                int t = m >> 6, b = m & 63;
                asrc = g_xh + ((size_t)b * TT + t) * II + ck * 64 + cg * 8;
            } else {
                asrc = g_ahist + (size_t)(m + 64) * HH + ck * 64 + cg * 8;
            }
            cp_async16(As + buf * (128 * 72) + row * 72 + cg * 8, asrc);
            cp_async16(Bs + buf * (128 * 72) + row * 72 + cg * 8,
                       Wg + (size_t)(n0 + row) * KD + ck * 64 + cg * 8);
        }
    };

    load_chunk(0, 0);
    cp_commit();
    for (int ck = 0; ck < NCHX; ++ck) {
        if (ck + 1 < NCHX) { load_chunk((ck + 1) & 1, ck + 1); cp_commit(); cp_wait1(); }
        else cp_wait0();
        __syncthreads();
        const __half* Ab = As + (ck & 1) * (128 * 72);
        const __half* Bb = Bs + (ck & 1) * (128 * 72);
#pragma unroll
        for (int s = 0; s < 4; ++s) {
            uint32_t a[2][4];
#pragma unroll
            for (int f = 0; f < 2; ++f)
                ldsm4(a[f][0], a[f][1], a[f][2], a[f][3],
                      Ab + (wm + f * 16 + arow) * 72 + s * 16 + akoff);
#pragma unroll
            for (int bp = 0; bp < 4; ++bp) {
                uint32_t b0, b1, b2, b3;
                ldsm4(b0, b1, b2, b3,
                      Bb + (wn + bp * 16 + brow) * 72 + s * 16 + bkoff);
#pragma unroll
                for (int f = 0; f < 2; ++f) {
                    mma16816(acc[f][2 * bp],     a[f], b0, b1);
                    mma16816(acc[f][2 * bp + 1], a[f], b2, b3);
                }
            }
        }
        __syncthreads();
    }

    float bs0[8], bs1[8];
#pragma unroll
    for (int bt = 0; bt < 8; ++bt) {
        int n = n0 + wn + bt * 8 + 2 * q;
        if (MODE == 0) { bs0[bt] = c0[n] + c1[n]; bs1[bt] = c0[n + 1] + c1[n + 1]; }
        else           { bs0[bt] = c0[n];         bs1[bt] = c0[n + 1]; }
    }
#pragma unroll
    for (int f = 0; f < 2; ++f) {
#pragma unroll
        for (int bt = 0; bt < 8; ++bt) {
            int mlo = wm + f * 16 + gr;
            int n = wn + bt * 8 + 2 * q;
            if (MODE == 0) {
                size_t zi = (size_t)(m0 + mlo) * HH + n0 + n;
                *(float2*)(g_Z + zi) =
                    make_float2(acc[f][bt][0] + bs0[bt], acc[f][bt][1] + bs1[bt]);
                *(float2*)(g_Z + zi + (size_t)8 * HH) =
                    make_float2(acc[f][bt][2] + bs0[bt], acc[f][bt][3] + bs1[bt]);
            } else {
                size_t oi = (size_t)(m0 + mlo) * OO + n0 + n;
                *(float2*)(outp + oi) =
                    make_float2(sigf(acc[f][bt][0] + bs0[bt]), sigf(acc[f][bt][1] + bs1[bt]));
                *(float2*)(outp + oi + (size_t)8 * OO) =
                    make_float2(sigf(acc[f][bt][2] + bs0[bt]), sigf(acc[f][bt][3] + bs1[bt]));
            }
        }
    }
}

// ---------------- persistent recurrence: aa ONLY, 128 CTAs ----------------
// 8 warps = 8 k-eighths (256 cols each); each warp computes the FULL m32 x n32
// tile -> 8 independent accumulator chains per warp (latency-hiding).
// Chunk = 32 cols per eighth, 8 chunks/step, ring-3, depth-2 prefetch.
// Epilogue: all 8 warps dump partials to smem; 256 threads reduce+sigmoid+store.
// Per-mh split release/acquire barrier.
#define NCTA_R 128
#define WPAD 2056
#define NCH 8
#define ASTR 264                                     // 8*32 + 8 pad
#define ABUFH (32 * ASTR)                            // 8448 halves = 16896 B
#define ZSTR 36
#define OFF_W 0
#define OFF_A (32 * WPAD * 2)                        // 131584
#define OFF_RED (OFF_A + 3 * ABUFH * 2)              // 131584 + 50688 = 182272
#define OFF_Z (OFF_RED + 8 * 32 * 32 * 4)            // + 32768 = 215040
#define PERS_SMEM (OFF_Z + 2 * 32 * ZSTR * 4)        // + 9216 = 224256

__global__ void __launch_bounds__(256) rnn_persistent() {
    extern __shared__ __align__(16) unsigned char smraw[];
    __half* Wsm = (__half*)(smraw + OFF_W);        // [32][WPAD]
    __half* Asm = (__half*)(smraw + OFF_A);        // [3][32][ASTR]
    float*  red = (float*)(smraw + OFF_RED);       // [8 kq][32][32]
    float*  Zsm = (float*)(smraw + OFF_Z);         // [2][32][ZSTR]

    const int tid = threadIdx.x;
    const int lane = tid & 31, warp = tid >> 5;
    const int cta = blockIdx.x;
    const int slice = cta & 63;
    const int mh = cta >> 6;                 // 0..1
    const int n0 = slice * 32;
    const int row0 = mh * 32;
    unsigned* barp = &g_barh[mh * 32];       // separate 128B lines per half

    // Z slice loader: 32 rows x 32 floats = 256 16B segs, 1/thread
    auto loadZ = [&](int it, int zb) {
        int row = tid >> 3, j = tid & 7;
        cp_async16(Zsm + zb * (32 * ZSTR) + row * ZSTR + j * 4,
                   g_Z + ((size_t)it * 64 + row0 + row) * HH + n0 + j * 4);
    };

    // persistent W_aa slice: 32 rows x 2048 halves; plus Z for step 0
    for (int u = tid; u < 32 * 256; u += 256) {
        int row = u >> 8, cg = u & 255;
        cp_async16(Wsm + row * WPAD + cg * 8, g_Waa + (size_t)(n0 + row) * HH + cg * 8);
    }
    loadZ(0, 0);
    cp_commit();
    cp_wait0();
    __syncthreads();

    const int kq = warp;               // 0..7 (k eighth, 256 cols each)
    const int gr = lane >> 2, q = lane & 3;
    const int arow = ((lane >> 3) & 1) * 8 + (lane & 7);
    const int akoff = (lane >> 4) * 8;
    const int brow = (lane >> 4) * 8 + (lane & 7);
    const int bkoff = ((lane >> 3) & 1) * 8;

    // chunk loader: 32 rows x (8 eighths x 32 cols) = 1024 16B segs, 4/thread
    auto loadA = [&](int buf, int c, const __half* a_src) {
#pragma unroll
        for (int r = 0; r < 4; ++r) {
            int idx = tid + r * 256;
            int row = idx >> 5, seg = idx & 31;
            int e = seg >> 2, j = seg & 3;
            cp_async16(Asm + buf * ABUFH + row * ASTR + e * 32 + j * 8,
                       a_src + (size_t)(row0 + row) * HH + e * 256 + c * 32 + j * 8);
        }
    };

    // epilogue indices: thread handles 4 consecutive cols of one row
    const int erow = tid >> 3;            // 0..31
    const int ecol = (tid & 7) * 4;       // 0,4,..,28

    for (int it = 0; it < TT; ++it) {
        const __half* a_cur = g_ahist + (size_t)it * NA0;
        const float* Zb = Zsm + (it & 1) * (32 * ZSTR);

        float acc[2][4][4];
#pragma unroll
        for (int f = 0; f < 2; ++f)
#pragma unroll
            for (int bs = 0; bs < 4; ++bs)
#pragma unroll
                for (int c = 0; c < 4; ++c) acc[f][bs][c] = 0.0f;

        loadA(0, 0, a_cur); cp_commit();
        loadA(1, 1, a_cur); cp_commit();

        for (int c = 0; c < NCH; ++c) {
            if (c < NCH - 1) cp_wait1(); else cp_wait0();
            __syncthreads();   // chunk c resident; all warps done with c-1
            if (c + 2 < NCH) { loadA((c + 2) % 3, c + 2, a_cur); cp_commit(); }

            const __half* Ab = Asm + (c % 3) * ABUFH;
#pragma unroll
            for (int s = 0; s < 2; ++s) {
                uint32_t a[2][4];
#pragma unroll
                for (int f = 0; f < 2; ++f)
                    ldsm4(a[f][0], a[f][1], a[f][2], a[f][3],
                          Ab + (f * 16 + arow) * ASTR + kq * 32 + s * 16 + akoff);
                int bcol = kq * 256 + c * 32 + s * 16 + bkoff;
                uint32_t bl0, bl1, bl2, bl3, bu0, bu1, bu2, bu3;
                ldsm4(bl0, bl1, bl2, bl3, Wsm + brow * WPAD + bcol);
                ldsm4(bu0, bu1, bu2, bu3, Wsm + (brow + 16) * WPAD + bcol);
#pragma unroll
                for (int f = 0; f < 2; ++f) {
                    mma16816(acc[f][0], a[f], bl0, bl1);
                    mma16816(acc[f][1], a[f], bl2, bl3);
                    mma16816(acc[f][2], a[f], bu0, bu1);
                    mma16816(acc[f][3], a[f], bu2, bu3);
                }
            }
        }

        // ---- all warps write partials ----
        {
            float* rp = red + (size_t)kq * 1024;
#pragma unroll
            for (int f = 0; f < 2; ++f)
#pragma unroll
                for (int bs = 0; bs < 4; ++bs) {
                    int row = f * 16 + gr, col = bs * 8 + 2 * q;
                    *(float2*)(rp + row * 32 + col) = make_float2(acc[f][bs][0], acc[f][bs][1]);
                    *(float2*)(rp + (row + 8) * 32 + col) = make_float2(acc[f][bs][2], acc[f][bs][3]);
                }
        }
        __syncthreads();

        // ---- distributed reduce + sigmoid + store (4 outputs/thread) ----
        {
            float4 sum = *(const float4*)(red + (size_t)erow * 32 + ecol);
#pragma unroll
            for (int p = 1; p < 8; ++p) {
                float4 v = *(const float4*)(red + (size_t)p * 1024 + erow * 32 + ecol);
                sum.x += v.x; sum.y += v.y; sum.z += v.z; sum.w += v.w;
            }
            float4 z = *(const float4*)(Zb + erow * ZSTR + ecol);
            __half2 h0 = __floats2half2_rn(sigf(sum.x + z.x), sigf(sum.y + z.y));
            __half2 h1 = __floats2half2_rn(sigf(sum.z + z.z), sigf(sum.w + z.w));
            __half* adst = g_ahist + (size_t)(it + 1) * NA0
                         + (size_t)(row0 + erow) * HH + n0 + ecol;
            *(uint2*)adst = make_uint2(*(uint32_t*)&h0, *(uint32_t*)&h1);
        }

        // prefetch next step's Z across the barrier (g_Z is static)
        if (it + 1 < TT) { loadZ(it + 1, (it + 1) & 1); cp_commit(); }

        // -------- per-half grid barrier (release/acquire, 64 arrivals) --------
        __syncthreads();                 // all stores of this CTA complete
        if (tid == 0) {
            red_rel_add1(barp);
            unsigned target = (unsigned)(it + 1) * 64u;
            while (ld_acq(barp) < target) { }
        }
        __syncthreads();
    }
}

// ---------------- launch ----------------
extern "C" void kernel_launch(void* const* d_in, const int* in_sizes, int n_in,
                              void* d_out, int out_size) {
    const float* x    = (const float*)d_in[0];
    const float* Waa  = (const float*)d_in[1];
    const float* b_aa = (const float*)d_in[2];
    const float* Wax  = (const float*)d_in[3];
    const float* b_ax = (const float*)d_in[4];
    const float* Wya  = (const float*)d_in[5];
    const float* b_ya = (const float*)d_in[6];
    float* out = (float*)d_out;

    static bool attr_done = false;
    if (!attr_done) {
        cudaFuncSetAttribute(big_gemm<0>, cudaFuncAttributeMaxDynamicSharedMemorySize, XP_SMEM);
        cudaFuncSetAttribute(big_gemm<1>, cudaFuncAttributeMaxDynamicSharedMemorySize, XP_SMEM);
        cudaFuncSetAttribute(rnn_persistent, cudaFuncAttributeMaxDynamicSharedMemorySize, PERS_SMEM);
        attr_done = true;
    }

    int prep_blocks = (int)((NPREP4 + 255) / 256);
    prep_kernel<<<prep_blocks, 256>>>(x, Waa, Wax, Wya);

    dim3 xg(HH / 128, (TT * BB) / 128);   // 16 x 128
    big_gemm<0><<<xg, 256, XP_SMEM>>>(b_ax, b_aa, nullptr);

    rnn_persistent<<<NCTA_R, 256, PERS_SMEM>>>();

    dim3 yg(OO / 128, (TT * BB) / 128);   // 8 x 128
    big_gemm<1><<<yg, 256, XP_SMEM>>>(b_ya, nullptr, out);
}